// round 11
// baseline (speedup 1.0000x reference)
#include <cuda_runtime.h>
#include <math.h>

#define N_MCMC 100000
#define N_DA   10000
#define N_ATT  60000
#define NOBS   256
#define FULLM  0xffffffffu

typedef unsigned long long u64;

// f32 basis computed on-device with libdevice sinf/cosf -- bitwise identical to
// XLA:GPU's __nv_sinf/__nv_cosf on the same GPU.
__device__ float g_S[NOBS], g_C[NOBS], g_S2[NOBS], g_Y[NOBS];

__global__ void k_zero(float* p, int n) {
    int i = blockIdx.x * blockDim.x + threadIdx.x;
    if (i < n) p[i] = 0.0f;
}

__global__ void k_basis(const float* __restrict__ loc, const float* __restrict__ val) {
    int j = threadIdx.x;
    const float pif   = 0x1.921fb6p+1f;   // f32(np.pi)
    const float twopi = 0x1.921fb6p+2f;   // 2*f32(pi), exact
    float x  = loc[j];
    float r1 = __fmul_rn(pif, x);
    float r2 = __fmul_rn(twopi, x);
    g_S[j]  = sinf(r1);
    g_C[j]  = cosf(r1);
    g_S2[j] = sinf(r2);
    g_Y[j]  = val[j];
}

__device__ __forceinline__ u64 pk2(float lo, float hi) {
    u64 r; asm("mov.b64 %0,{%1,%2};" : "=l"(r)
               : "r"(__float_as_uint(lo)), "r"(__float_as_uint(hi)));
    return r;
}

// 16-leaf balanced tree (offsets 8,4,2,1), scalar FADDs only. With leaves
// u[j] = v[2j] (resp. v[2j+1]) this reproduces exactly the even (resp. odd)
// subtree of lane 0's shfl-down butterfly path: the butterfly's v-offsets
// 16,8,4,2 act as j-offsets 8,4,2,1 on the parity class. S = E + O is the
// butterfly's final off=1 add -> bitwise identical to XLA's warp reduce.
__device__ __forceinline__ float tree16(const float* __restrict__ sm) {
    float v[16];
    #pragma unroll
    for (int j = 0; j < 4; j++) {
        float4 q = reinterpret_cast<const float4*>(sm)[j];
        v[4*j+0] = q.x; v[4*j+1] = q.y; v[4*j+2] = q.z; v[4*j+3] = q.w;
    }
    #pragma unroll
    for (int off = 8; off >= 1; off >>= 1) {
        #pragma unroll
        for (int t = 0; t < off; t++)
            v[t] = __fadd_rn(v[t], v[t + off]);
    }
    return v[0];
}

__device__ __forceinline__ float lprior(float t0, float t1) {
    return __fmul_rn(-0.5f, __fadd_rn(__fmul_rn(t0, t0), __fmul_rn(t1, t1)));
}

// (-0.5*S)/0.25 == exactly -2*S (exact exponent shifts; quotient exactly
// representable so div.rn returns it). One FMUL, identical bits. (R10-proven.)
__device__ __forceinline__ float ll_from_sum(float S) {
    return __fmul_rn(-2.0f, S);
}

__device__ __forceinline__ float expm(float x) {
    return expf(fminf(x, 0.0f));          // min.f32 + __nv_expf, as XLA emits
}

// Markstein correctly-rounded division with precomputed RN reciprocal:
// r = RN(1/den) (__frcp_rn), q0 = RN(num*r), e = fma(-den,q0,num),
// q = fma(e,r,q0) == RN(num/den) == __fdiv_rn(num, den) for normal values.
__device__ __forceinline__ float div_rn_fast(float num, float den, float r) {
    float q0 = __fmul_rn(num, r);
    float e  = __fmaf_rn(-den, q0, num);
    return __fmaf_rn(e, r, q0);
}

__global__ void __launch_bounds__(32, 1) k_mcmc(
    const float* __restrict__ theta0,
    const float* __restrict__ eps_o, const float* __restrict__ u_o,
    const float* __restrict__ eps_d, const float* __restrict__ u_d,
    float* __restrict__ out)
{
    // Double-buffered (stride 80) leaf-exchange slots. Per buffer:
    // [0..16)  even-outer  [16..32) odd-outer
    // [36..52) even-inner  [52..68) odd-inner   (bases 0/64/144/208 B: disjoint
    // 16B-aligned bank groups -> conflict-free 4-way broadcast loads)
    __shared__ __align__(16) float red[160];
    int lane = threadIdx.x;
    int permO = ((lane & 1) << 4) + (lane >> 1);        // v[t] -> parity slot
    int permI = 36 + permO;

    // Per-lane basis registers. k = 2*i + v  <->  j = 64*i + 2*lane + v:
    // XLA's vectorized (vec=2) row-reduce per-thread order.
    float bS[8], bC[8], bS2[8], bY[8];
    #pragma unroll
    for (int k = 0; k < 8; k++) {
        int j = 64 * (k >> 1) + 2 * lane + (k & 1);
        bS[k] = g_S[j]; bC[k] = g_C[j]; bS2[k] = g_S2[j]; bY[k] = g_Y[j];
    }

    // All 32 lanes carry identical scalar chain state.
    float th0 = theta0[0], th1 = theta0[1];
    float dt = 0.1f;

    // Initial lpost_o(theta0)
    float lpT;
    {
        float acc = 0.0f;
        #pragma unroll
        for (int k = 0; k < 8; k++) {
            float p = __fadd_rn(__fmul_rn(th0, bS[k]), __fmul_rn(th1, bC[k]));
            float d = __fsub_rn(bY[k], p);
            acc = __fadd_rn(acc, __fmul_rn(d, d));
        }
        red[permO] = acc;
        __syncwarp();
        float s = tree16(red + ((lane >> 4) << 4));
        float E = __shfl_sync(FULLM, s, 0);
        float O = __shfl_sync(FULLM, s, 16);
        lpT = __fadd_rn(lprior(th0, th1), ll_from_sum(__fadd_rn(E, O)));
        __syncwarp();
    }

    // ---------------- Stage 1: adaptive RW-MH ----------------
    float e0 = __ldg(&eps_o[0]), e1 = __ldg(&eps_o[1]), uu = __ldg(&u_o[0]);
    float fi = 0.0f;                                  // == (float)i, exact
    float rcp = __frcp_rn(1.0f);                      // RN(1/(fi+1)) for i=0
    for (int i = 0; i < N_MCMC; i++) {
        float* buf = red + (i & 1) * 80;
        float p0 = __fadd_rn(th0, __fmul_rn(dt, e0));
        float p1 = __fadd_rn(th1, __fmul_rn(dt, e1));
        // off-critical-path: RN reciprocal for NEXT iteration's dt update
        float rNext = __frcp_rn(__fadd_rn(fi, 2.0f));
        float acc = 0.0f;
        #pragma unroll
        for (int k = 0; k < 8; k++) {
            float p = __fadd_rn(__fmul_rn(p0, bS[k]), __fmul_rn(p1, bC[k]));
            float d = __fsub_rn(bY[k], p);
            acc = __fadd_rn(acc, __fmul_rn(d, d));
        }
        // prefetch next randoms while the exchange+tree runs
        float ne0 = 0.f, ne1 = 0.f, nu = 0.f;
        if (i + 1 < N_MCMC) {
            ne0 = __ldg(&eps_o[2 * i + 2]);
            ne1 = __ldg(&eps_o[2 * i + 3]);
            nu  = __ldg(&u_o[i + 1]);
        }
        buf[permO] = acc;
        __syncwarp();
        // half-warp split tree: lanes 0-15 even subtree, 16-31 odd subtree
        float s = tree16(buf + ((lane >> 4) << 4));
        float E = __shfl_sync(FULLM, s, 0);
        float O = __shfl_sync(FULLM, s, 16);
        float S = __fadd_rn(E, O);
        float lpP = __fadd_rn(lprior(p0, p1), ll_from_sum(S));
        float a   = expm(__fsub_rn(lpP, lpT));
        if (uu < a) { th0 = p0; th1 = p1; lpT = lpP; }
        float num = __fmul_rn(dt, __fsub_rn(a, 0.234f));
        float den = __fadd_rn(fi, 1.0f);
        dt = __fadd_rn(dt, div_rn_fast(num, den, rcp));
        fi = den;                                      // fi+1, exact
        rcp = rNext;
        e0 = ne0; e1 = ne1; uu = nu;
    }
    __syncwarp();

    // ---------------- Stage 2: delayed acceptance ----------------
    // Cached lpost_o/lpost_i at current theta (bitwise == per-step recompute).
    float lpTo, lpTi;
    {
        float kk = __fmul_rn(__fmul_rn(0.05f, th0), th1);
        float aO = 0.0f, aI = 0.0f;
        #pragma unroll
        for (int k = 0; k < 8; k++) {
            float p   = __fadd_rn(__fmul_rn(th0, bS[k]), __fmul_rn(th1, bC[k]));
            float pi_ = __fadd_rn(p, __fmul_rn(kk, bS2[k]));
            float dO = __fsub_rn(bY[k], p);   aO = __fadd_rn(aO, __fmul_rn(dO, dO));
            float dI = __fsub_rn(bY[k], pi_); aI = __fadd_rn(aI, __fmul_rn(dI, dI));
        }
        red[permO] = aO; red[permI] = aI;
        __syncwarp();
        int g = lane >> 3;
        float s = tree16(red + (g & 1) * 16 + (g >> 1) * 36);
        float EO = __shfl_sync(FULLM, s, 0);
        float OO = __shfl_sync(FULLM, s, 8);
        float EI = __shfl_sync(FULLM, s, 16);
        float OI = __shfl_sync(FULLM, s, 24);
        float lpr = lprior(th0, th1);
        lpTo = __fadd_rn(lpr, ll_from_sum(__fadd_rn(EO, OO)));
        lpTi = __fadd_rn(lpr, ll_from_sum(__fadd_rn(EI, OI)));
        __syncwarp();
    }

    float* out_acc = out;                               // [10000]
    float* out_th  = out + N_DA;                        // [10000,2]
    float* out_nn  = out + N_DA + 2 * N_DA;             // [10000,256]
    float* out_sol = out_nn + (size_t)N_DA * NOBS;      // [10000,256]

    int mh = 0;
    float de0 = __ldg(&eps_d[0]), de1 = __ldg(&eps_d[1]);
    float du0 = __ldg(&u_d[0]),  du1 = __ldg(&u_d[1]);
    for (int i = 0; i < N_ATT && mh < N_DA; i++) {
        float* buf = red + (i & 1) * 80;
        float p0 = __fadd_rn(th0, __fmul_rn(dt, de0));
        float p1 = __fadd_rn(th1, __fmul_rn(dt, de1));
        float kk = __fmul_rn(__fmul_rn(0.05f, p0), p1);
        float rO[8], rI[8];
        float aO = 0.0f, aI = 0.0f;
        #pragma unroll
        for (int k = 0; k < 8; k++) {
            float p   = __fadd_rn(__fmul_rn(p0, bS[k]), __fmul_rn(p1, bC[k]));
            float pi_ = __fadd_rn(p, __fmul_rn(kk, bS2[k]));
            rO[k] = p; rI[k] = pi_;
            float dO = __fsub_rn(bY[k], p);   aO = __fadd_rn(aO, __fmul_rn(dO, dO));
            float dI = __fsub_rn(bY[k], pi_); aI = __fadd_rn(aI, __fmul_rn(dI, dI));
        }
        float nde0 = 0.f, nde1 = 0.f, ndu0 = 0.f, ndu1 = 0.f;
        if (i + 1 < N_ATT) {
            nde0 = __ldg(&eps_d[2 * i + 2]);
            nde1 = __ldg(&eps_d[2 * i + 3]);
            ndu0 = __ldg(&u_d[2 * i + 2]);
            ndu1 = __ldg(&u_d[2 * i + 3]);
        }
        buf[permO] = aO; buf[permI] = aI;
        __syncwarp();
        // 4-way split: lane groups of 8 compute E_O/O_O/E_I/O_I in one stream
        int g = lane >> 3;
        float s = tree16(buf + (g & 1) * 16 + (g >> 1) * 36);
        float EO = __shfl_sync(FULLM, s, 0);
        float OO = __shfl_sync(FULLM, s, 8);
        float EI = __shfl_sync(FULLM, s, 16);
        float OI = __shfl_sync(FULLM, s, 24);
        float lpr  = lprior(p0, p1);
        float lpPo = __fadd_rn(lpr, ll_from_sum(__fadd_rn(EO, OO)));
        float lpPi = __fadd_rn(lpr, ll_from_sum(__fadd_rn(EI, OI)));
        // ((lpost_i(prop) - lpost_i(theta)) + lo) - lp  (Python left-assoc)
        float t = __fsub_rn(lpPi, lpTi);
        t = __fadd_rn(t, lpTo);
        t = __fsub_rn(t, lpPo);
        // two expf's concurrently on opposite half-warps (same code path ->
        // same bits), then exchange
        float m1 = fminf(__fsub_rn(lpPo, lpTo), 0.0f);
        float m2 = fminf(t, 0.0f);
        float ev = expf((lane < 16) ? m1 : m2);
        float a  = __shfl_sync(FULLM, ev, 0);
        float a2 = __shfl_sync(FULLM, ev, 16);
        bool active = (du0 < a);              // mh < N_DA via loop condition
        bool inner  = active && (du1 < a2);
        if (active) {
            if (lane == 0) {
                out_acc[mh] = inner ? 1.0f : 0.0f;
                *reinterpret_cast<u64*>(out_th + 2 * mh) = pk2(p0, p1);
            }
            float* nn = out_nn  + (size_t)mh * NOBS;
            float* sl = out_sol + (size_t)mh * NOBS;
            #pragma unroll
            for (int k = 0; k < 8; k += 2) {
                int j0 = 64 * (k >> 1) + 2 * lane;     // 8B-aligned adjacent pair
                *reinterpret_cast<u64*>(nn + j0) = pk2(rO[k], rO[k + 1]);
                *reinterpret_cast<u64*>(sl + j0) = pk2(rI[k], rI[k + 1]);
            }
            mh++;
        }
        if (inner) { th0 = p0; th1 = p1; lpTo = lpPo; lpTi = lpPi; }
        de0 = nde0; de1 = nde1; du0 = ndu0; du1 = ndu1;
    }
}

extern "C" void kernel_launch(void* const* d_in, const int* in_sizes, int n_in,
                              void* d_out, int out_size) {
    const float* obs_loc = (const float*)d_in[0];
    const float* obs_val = (const float*)d_in[1];
    const float* theta0  = (const float*)d_in[2];
    const float* eps_o   = (const float*)d_in[3];
    const float* u_o     = (const float*)d_in[4];
    const float* eps_d   = (const float*)d_in[5];
    const float* u_d     = (const float*)d_in[6];
    float* out = (float*)d_out;

    k_zero<<<(out_size + 255) / 256, 256>>>(out, out_size);
    k_basis<<<1, NOBS>>>(obs_loc, obs_val);
    k_mcmc<<<1, 32>>>(theta0, eps_o, u_o, eps_d, u_d, out);
}

// round 12
// speedup vs baseline: 1.0797x; 1.0797x over previous
#include <cuda_runtime.h>
#include <math.h>

#define N_MCMC 100000
#define N_DA   10000
#define N_ATT  60000
#define NOBS   256
#define FULLM  0xffffffffu

typedef unsigned long long u64;

// f32 basis computed on-device with libdevice sinf/cosf -- bitwise identical to
// XLA:GPU's __nv_sinf/__nv_cosf on the same GPU.
__device__ float g_S[NOBS], g_C[NOBS], g_S2[NOBS], g_Y[NOBS];

__global__ void k_zero(float* p, int n) {
    int i = blockIdx.x * blockDim.x + threadIdx.x;
    if (i < n) p[i] = 0.0f;
}

__global__ void k_basis(const float* __restrict__ loc, const float* __restrict__ val) {
    int j = threadIdx.x;
    const float pif   = 0x1.921fb6p+1f;   // f32(np.pi)
    const float twopi = 0x1.921fb6p+2f;   // 2*f32(pi), exact
    float x  = loc[j];
    float r1 = __fmul_rn(pif, x);
    float r2 = __fmul_rn(twopi, x);
    g_S[j]  = sinf(r1);
    g_C[j]  = cosf(r1);
    g_S2[j] = sinf(r2);
    g_Y[j]  = val[j];
}

__device__ __forceinline__ u64 pk2(float lo, float hi) {
    u64 r; asm("mov.b64 %0,{%1,%2};" : "=l"(r)
               : "r"(__float_as_uint(lo)), "r"(__float_as_uint(hi)));
    return r;
}

// Bitwise-identical add/sub via FFMA with immediate multiplier (rt_SMSP=1 vs 2):
// fma.rn(a,1,b): a*1 is exact, single rounding of a+b == add.rn(a,b).
// fma.rn(b,-1,a): single rounding of a-b == sub.rn(a,b). Holds for all inputs.
__device__ __forceinline__ float addx(float a, float b) { return __fmaf_rn(a,  1.0f, b); }
__device__ __forceinline__ float subx(float a, float b) { return __fmaf_rn(b, -1.0f, a); }  // a-b

// In-register 32-leaf reduction tree (R10-proven shape; FFMA-imm adds).
// Executes exactly the adds on lane 0's path of the shfl-down butterfly
// (offsets 16,8,4,2,1): bitwise identical to XLA's warp reduce.
__device__ __forceinline__ float tree32(const float* __restrict__ sm) {
    float v[32];
    #pragma unroll
    for (int j = 0; j < 8; j++) {
        float4 q = reinterpret_cast<const float4*>(sm)[j];
        v[4*j+0] = q.x; v[4*j+1] = q.y; v[4*j+2] = q.z; v[4*j+3] = q.w;
    }
    #pragma unroll
    for (int off = 16; off >= 1; off >>= 1) {
        #pragma unroll
        for (int t = 0; t < off; t++)
            v[t] = addx(v[t], v[t + off]);
    }
    return v[0];
}

__device__ __forceinline__ float lprior(float t0, float t1) {
    return __fmul_rn(-0.5f, addx(__fmul_rn(t0, t0), __fmul_rn(t1, t1)));
}

// (-0.5*S)/0.25 == exactly -2*S (exact exponent shifts; quotient exactly
// representable so div.rn returns it). One FMUL, identical bits. (R10-proven.)
__device__ __forceinline__ float ll_from_sum(float S) {
    return __fmul_rn(-2.0f, S);
}

__device__ __forceinline__ float expm(float x) {
    return expf(fminf(x, 0.0f));          // min.f32 + __nv_expf, as XLA emits
}

__global__ void __launch_bounds__(32, 1) k_mcmc(
    const float* __restrict__ theta0,
    const float* __restrict__ eps_o, const float* __restrict__ u_o,
    const float* __restrict__ eps_d, const float* __restrict__ u_d,
    float* __restrict__ out)
{
    // Double-buffered leaf-exchange slots (parity toggle avoids WAR syncwarp).
    __shared__ __align__(16) float red[128];
    int lane = threadIdx.x;

    // Per-lane basis registers. k = 2*i + v  <->  j = 64*i + 2*lane + v:
    // XLA's vectorized (vec=2) row-reduce per-thread order.
    float bS[8], bC[8], bS2[8], bY[8];
    #pragma unroll
    for (int k = 0; k < 8; k++) {
        int j = 64 * (k >> 1) + 2 * lane + (k & 1);
        bS[k] = g_S[j]; bC[k] = g_C[j]; bS2[k] = g_S2[j]; bY[k] = g_Y[j];
    }

    // All 32 lanes carry identical scalar chain state.
    float th0 = theta0[0], th1 = theta0[1];
    float dt = 0.1f;

    // Initial lpost_o(theta0)
    float acc0 = 0.0f;
    #pragma unroll
    for (int k = 0; k < 8; k++) {
        float p = addx(__fmul_rn(th0, bS[k]), __fmul_rn(th1, bC[k]));
        float d = subx(bY[k], p);
        acc0 = addx(acc0, __fmul_rn(d, d));
    }
    red[lane] = acc0;
    __syncwarp();
    float lpT = addx(lprior(th0, th1), ll_from_sum(tree32(red)));
    __syncwarp();

    // ---------------- Stage 1: adaptive RW-MH ----------------
    float e0 = __ldg(&eps_o[0]), e1 = __ldg(&eps_o[1]), uu = __ldg(&u_o[0]);
    float fi = 0.0f;                                  // == (float)i, exact
    for (int i = 0; i < N_MCMC; i++) {
        float* buf = red + ((i & 1) << 5);
        float p0 = addx(th0, __fmul_rn(dt, e0));
        float p1 = addx(th1, __fmul_rn(dt, e1));
        float a2c = 0.0f;
        #pragma unroll
        for (int k = 0; k < 8; k++) {
            float p = addx(__fmul_rn(p0, bS[k]), __fmul_rn(p1, bC[k]));
            float d = subx(bY[k], p);
            a2c = addx(a2c, __fmul_rn(d, d));
        }
        // prefetch next randoms while the exchange+tree runs
        float ne0 = 0.f, ne1 = 0.f, nu = 0.f;
        if (i + 1 < N_MCMC) {
            ne0 = __ldg(&eps_o[2 * i + 2]);
            ne1 = __ldg(&eps_o[2 * i + 3]);
            nu  = __ldg(&u_o[i + 1]);
        }
        buf[lane] = a2c;
        __syncwarp();
        float S = tree32(buf);                         // identical in all lanes
        float lpP = addx(lprior(p0, p1), ll_from_sum(S));
        float a   = expm(subx(lpP, lpT));
        if (uu < a) { th0 = p0; th1 = p1; lpT = lpP; }
        dt = addx(dt, __fdiv_rn(__fmul_rn(dt, subx(a, 0.234f)),
                                addx(fi, 1.0f)));
        fi = addx(fi, 1.0f);
        e0 = ne0; e1 = ne1; uu = nu;
    }
    __syncwarp();

    // ---------------- Stage 2: delayed acceptance ----------------
    // Cached lpost_o/lpost_i at current theta (bitwise == per-step recompute).
    float lpTo, lpTi;
    {
        float kk = __fmul_rn(__fmul_rn(0.05f, th0), th1);
        float aO = 0.0f, aI = 0.0f;
        #pragma unroll
        for (int k = 0; k < 8; k++) {
            float p   = addx(__fmul_rn(th0, bS[k]), __fmul_rn(th1, bC[k]));
            float pi_ = addx(p, __fmul_rn(kk, bS2[k]));
            float dO = subx(bY[k], p);   aO = addx(aO, __fmul_rn(dO, dO));
            float dI = subx(bY[k], pi_); aI = addx(aI, __fmul_rn(dI, dI));
        }
        red[lane] = aO; red[32 + lane] = aI;
        __syncwarp();
        float lpr = lprior(th0, th1);
        lpTo = addx(lpr, ll_from_sum(tree32(red)));
        lpTi = addx(lpr, ll_from_sum(tree32(red + 32)));
        __syncwarp();
    }

    float* out_acc = out;                               // [10000]
    float* out_th  = out + N_DA;                        // [10000,2]
    float* out_nn  = out + N_DA + 2 * N_DA;             // [10000,256]
    float* out_sol = out_nn + (size_t)N_DA * NOBS;      // [10000,256]

    int mh = 0;
    float de0 = __ldg(&eps_d[0]), de1 = __ldg(&eps_d[1]);
    float du0 = __ldg(&u_d[0]),  du1 = __ldg(&u_d[1]);
    for (int i = 0; i < N_ATT && mh < N_DA; i++) {
        float* buf = red + ((i & 1) << 6);
        float p0 = addx(th0, __fmul_rn(dt, de0));
        float p1 = addx(th1, __fmul_rn(dt, de1));
        float kk = __fmul_rn(__fmul_rn(0.05f, p0), p1);
        float rO[8], rI[8];
        float aO = 0.0f, aI = 0.0f;
        #pragma unroll
        for (int k = 0; k < 8; k++) {
            float p   = addx(__fmul_rn(p0, bS[k]), __fmul_rn(p1, bC[k]));
            float pi_ = addx(p, __fmul_rn(kk, bS2[k]));
            rO[k] = p; rI[k] = pi_;
            float dO = subx(bY[k], p);   aO = addx(aO, __fmul_rn(dO, dO));
            float dI = subx(bY[k], pi_); aI = addx(aI, __fmul_rn(dI, dI));
        }
        float nde0 = 0.f, nde1 = 0.f, ndu0 = 0.f, ndu1 = 0.f;
        if (i + 1 < N_ATT) {
            nde0 = __ldg(&eps_d[2 * i + 2]);
            nde1 = __ldg(&eps_d[2 * i + 3]);
            ndu0 = __ldg(&u_d[2 * i + 2]);
            ndu1 = __ldg(&u_d[2 * i + 3]);
        }
        buf[lane] = aO; buf[32 + lane] = aI;
        __syncwarp();
        // Half-warp split: lanes 0-15 run the outer tree, 16-31 the inner tree
        // (same instruction stream, different smem base), then broadcast both.
        float s = tree32(buf + ((lane < 16) ? 0 : 32));
        float SO = __shfl_sync(FULLM, s, 0);
        float SI = __shfl_sync(FULLM, s, 16);
        float lpr  = lprior(p0, p1);
        float lpPo = addx(lpr, ll_from_sum(SO));
        float lpPi = addx(lpr, ll_from_sum(SI));
        // ((lpost_i(prop) - lpost_i(theta)) + lo) - lp  (Python left-assoc)
        float t = subx(lpPi, lpTi);
        t = addx(t, lpTo);
        t = subx(t, lpPo);
        // two expf's concurrently on opposite half-warps (identical code path
        // -> identical bits), then exchange
        float m1 = fminf(subx(lpPo, lpTo), 0.0f);
        float m2 = fminf(t, 0.0f);
        float ev = expf((lane < 16) ? m1 : m2);
        float a  = __shfl_sync(FULLM, ev, 0);
        float a2 = __shfl_sync(FULLM, ev, 16);
        bool active = (du0 < a);              // mh < N_DA via loop condition
        bool inner  = active && (du1 < a2);
        if (active) {
            if (lane == 0) {
                out_acc[mh] = inner ? 1.0f : 0.0f;
                *reinterpret_cast<u64*>(out_th + 2 * mh) = pk2(p0, p1);
            }
            float* nn = out_nn  + (size_t)mh * NOBS;
            float* sl = out_sol + (size_t)mh * NOBS;
            #pragma unroll
            for (int k = 0; k < 8; k += 2) {
                int j0 = 64 * (k >> 1) + 2 * lane;     // 8B-aligned adjacent pair
                *reinterpret_cast<u64*>(nn + j0) = pk2(rO[k], rO[k + 1]);
                *reinterpret_cast<u64*>(sl + j0) = pk2(rI[k], rI[k + 1]);
            }
            mh++;
        }
        if (inner) { th0 = p0; th1 = p1; lpTo = lpPo; lpTi = lpPi; }
        de0 = nde0; de1 = nde1; du0 = ndu0; du1 = ndu1;
    }
}

extern "C" void kernel_launch(void* const* d_in, const int* in_sizes, int n_in,
                              void* d_out, int out_size) {
    const float* obs_loc = (const float*)d_in[0];
    const float* obs_val = (const float*)d_in[1];
    const float* theta0  = (const float*)d_in[2];
    const float* eps_o   = (const float*)d_in[3];
    const float* u_o     = (const float*)d_in[4];
    const float* eps_d   = (const float*)d_in[5];
    const float* u_d     = (const float*)d_in[6];
    float* out = (float*)d_out;

    k_zero<<<(out_size + 255) / 256, 256>>>(out, out_size);
    k_basis<<<1, NOBS>>>(obs_loc, obs_val);
    k_mcmc<<<1, 32>>>(theta0, eps_o, u_o, eps_d, u_d, out);
}